// round 1
// baseline (speedup 1.0000x reference)
#include <cuda_runtime.h>
#include <math.h>

#define Bq   16
#define Cq   256
#define HWq  16384
#define INTERq 128

// scratch: per-block partial channel sums from K1
__device__ float g_scratch[Bq * 32 * Cq];   // [b][blk(32)][c] = 512 KB
__device__ float g_p[Bq * Cq];              // pooled means
__device__ int   g_idx[Bq * 3];             // top-3 channel ids per sample

__device__ __forceinline__ float gelu_exact(float v) {
    return 0.5f * v * (1.0f + erff(v * 0.70710678118654752f));
}

// ---------------------------------------------------------------------------
// K1: fused streaming pass over x.
//   grid = B*32 blocks, 128 threads, each thread handles 4 floats (float4).
//   For its 512-float spatial chunk, loops c=0..255:
//     - accumulates W3-weighted sum per pixel (for x3 / GELU, out channel 0)
//     - warp-reduces the chunk sum per channel -> block partial -> g_scratch
// ---------------------------------------------------------------------------
__global__ __launch_bounds__(128) void k1_fused(const float* __restrict__ x,
                                                const float* __restrict__ W3,
                                                float* __restrict__ out) {
    __shared__ float sw3[Cq];
    __shared__ float sps[Cq * 4];   // per-(c, warp) partials

    const int b   = blockIdx.x >> 5;
    const int blk = blockIdx.x & 31;
    const int t    = threadIdx.x;        // 0..127
    const int lane = t & 31;
    const int warp = t >> 5;

    for (int i = t; i < Cq; i += 128) sw3[i] = W3[i];
    __syncthreads();

    const size_t base = (size_t)b * Cq * HWq + (size_t)blk * 512 + (size_t)t * 4;

    float4 acc = make_float4(0.f, 0.f, 0.f, 0.f);

    #pragma unroll 4
    for (int c = 0; c < Cq; ++c) {
        const float4 v = *reinterpret_cast<const float4*>(x + base + (size_t)c * HWq);
        const float w = sw3[c];
        acc.x = fmaf(v.x, w, acc.x);
        acc.y = fmaf(v.y, w, acc.y);
        acc.z = fmaf(v.z, w, acc.z);
        acc.w = fmaf(v.w, w, acc.w);

        float s = (v.x + v.y) + (v.z + v.w);
        s += __shfl_down_sync(0xffffffffu, s, 16);
        s += __shfl_down_sync(0xffffffffu, s, 8);
        s += __shfl_down_sync(0xffffffffu, s, 4);
        s += __shfl_down_sync(0xffffffffu, s, 2);
        s += __shfl_down_sync(0xffffffffu, s, 1);
        if (lane == 0) sps[c * 4 + warp] = s;
    }
    __syncthreads();

    // write block partial sums: g_scratch[b][blk][c]
    for (int c = t; c < Cq; c += 128) {
        g_scratch[((size_t)(b * 32 + blk)) * Cq + c] =
            (sps[c * 4 + 0] + sps[c * 4 + 1]) + (sps[c * 4 + 2] + sps[c * 4 + 3]);
    }

    // x3 = gelu(sum_c x*W3) -> output channel 0
    float4 o;
    o.x = gelu_exact(acc.x);
    o.y = gelu_exact(acc.y);
    o.z = gelu_exact(acc.z);
    o.w = gelu_exact(acc.w);
    *reinterpret_cast<float4*>(out + (size_t)b * 4 * HWq + (size_t)blk * 512 + (size_t)t * 4) = o;
}

// ---------------------------------------------------------------------------
// K2a: reduce 32 partials per (b,c) -> pooled mean p. grid = 16 x 256 threads.
// ---------------------------------------------------------------------------
__global__ __launch_bounds__(256) void k2a_reduce() {
    const int i = blockIdx.x * 256 + threadIdx.x;   // i = b*256 + c
    const int b = i >> 8;
    const int c = i & 255;
    float s = 0.f;
    #pragma unroll
    for (int k = 0; k < 32; ++k)
        s += g_scratch[((size_t)(b * 32 + k)) * Cq + c];
    g_p[i] = s * (1.0f / (float)HWq);
}

// ---------------------------------------------------------------------------
// K2b: full small pipeline in one block (256 threads).
//   projections g/theta/phi, f = relu([th,ph] @ Wf^T + bf), y = f*g,
//   wy = y @ Wz^T + bz, batch-norm (train), residual + p, top-3 per sample.
// ---------------------------------------------------------------------------
__global__ __launch_bounds__(256) void k2b_pipeline(
    const float* __restrict__ Wg, const float* __restrict__ bg,
    const float* __restrict__ Wt, const float* __restrict__ bt,
    const float* __restrict__ Wp, const float* __restrict__ bp,
    const float* __restrict__ Wf, const float* __restrict__ bf,
    const float* __restrict__ Wz, const float* __restrict__ bz,
    const float* __restrict__ gamma, const float* __restrict__ beta)
{
    __shared__ float sp[Bq * Cq];     // pooled p        (16 KB)
    __shared__ float sgx[Bq * INTERq];// g_x             (8 KB)
    __shared__ float sab[Bq * Cq];    // th|ph, then wy/z (16 KB)
    __shared__ float sf[Bq];

    const int t = threadIdx.x; // 256 threads

    for (int i = t; i < Bq * Cq; i += 256) sp[i] = g_p[i];
    __syncthreads();

    // projections: threads 0..127 -> Wg column, threads 128..255 -> Wt column
    {
        const int col = t & 127;
        const float* W = (t < 128) ? Wg : Wt;
        float acc[Bq];
        #pragma unroll
        for (int b = 0; b < Bq; ++b) acc[b] = 0.f;
        for (int c = 0; c < Cq; ++c) {
            const float w = W[col * Cq + c];
            #pragma unroll
            for (int b = 0; b < Bq; ++b) acc[b] = fmaf(sp[b * Cq + c], w, acc[b]);
        }
        if (t < 128) {
            const float bias = bg[col];
            #pragma unroll
            for (int b = 0; b < Bq; ++b) sgx[b * INTERq + col] = acc[b] + bias;
        } else {
            const float bias = bt[col];
            #pragma unroll
            for (int b = 0; b < Bq; ++b) sab[b * Cq + col] = acc[b] + bias;   // theta
        }
    }
    // phi: threads 0..127
    if (t < 128) {
        float acc[Bq];
        #pragma unroll
        for (int b = 0; b < Bq; ++b) acc[b] = 0.f;
        for (int c = 0; c < Cq; ++c) {
            const float w = Wp[t * Cq + c];
            #pragma unroll
            for (int b = 0; b < Bq; ++b) acc[b] = fmaf(sp[b * Cq + c], w, acc[b]);
        }
        const float bias = bp[t];
        #pragma unroll
        for (int b = 0; b < Bq; ++b) sab[b * Cq + 128 + t] = acc[b] + bias;   // phi
    }
    __syncthreads();

    // f[b] = relu( [th,ph] . Wf + bf )
    if (t < Bq) {
        float s = bf[0];
        for (int i = 0; i < 2 * INTERq; ++i) s = fmaf(sab[t * Cq + i], Wf[i], s);
        sf[t] = fmaxf(s, 0.f);
    }
    __syncthreads();

    // wy[b][t] = f[b] * (g_x[b] . Wz[t]) + bz[t]   (overwrite sab)
    {
        float acc[Bq];
        #pragma unroll
        for (int b = 0; b < Bq; ++b) acc[b] = 0.f;
        for (int i = 0; i < INTERq; ++i) {
            const float w = Wz[t * INTERq + i];
            #pragma unroll
            for (int b = 0; b < Bq; ++b) acc[b] = fmaf(sgx[b * INTERq + i], w, acc[b]);
        }
        const float bias = bz[t];
        #pragma unroll
        for (int b = 0; b < Bq; ++b) sab[b * Cq + t] = fmaf(sf[b], acc[b], bias);
    }
    __syncthreads();

    // BatchNorm over batch (two-pass variance, matches jnp.var), residual + p
    {
        float m = 0.f;
        #pragma unroll
        for (int b = 0; b < Bq; ++b) m += sab[b * Cq + t];
        m *= (1.0f / (float)Bq);
        float var = 0.f;
        #pragma unroll
        for (int b = 0; b < Bq; ++b) {
            const float d = sab[b * Cq + t] - m;
            var = fmaf(d, d, var);
        }
        var *= (1.0f / (float)Bq);
        const float inv = rsqrtf(var + 1e-5f);
        const float ga = gamma[t], be = beta[t];
        #pragma unroll
        for (int b = 0; b < Bq; ++b) {
            const float z = fmaf(ga * (sab[b * Cq + t] - m), inv, be) + sp[b * Cq + t];
            sab[b * Cq + t] = z;   // sigmoid is monotone -> top-k on z == top-k on scores
        }
    }
    __syncthreads();

    // top-3 per sample (strict > : lowest index wins ties, matches lax.top_k)
    if (t < Bq) {
        const int bi = t * Cq;
        for (int j = 0; j < 3; ++j) {
            float best = -INFINITY;
            int   bidx = 0;
            for (int c = 0; c < Cq; ++c) {
                const float v = sab[bi + c];
                if (v > best) { best = v; bidx = c; }
            }
            g_idx[t * 3 + j] = bidx;
            sab[bi + bidx] = -INFINITY;
        }
    }
}

// ---------------------------------------------------------------------------
// K3: gather top-3 channels into output channels 1..3. grid = 16*3*16 blocks.
// ---------------------------------------------------------------------------
__global__ __launch_bounds__(256) void k3_gather(const float* __restrict__ x,
                                                 float* __restrict__ out) {
    const int q    = blockIdx.x >> 4;   // (b*3 + j)
    const int part = blockIdx.x & 15;
    const int b = q / 3, j = q % 3;
    const int ch = g_idx[b * 3 + j];
    const size_t pos = (size_t)part * 1024 + (size_t)threadIdx.x * 4;
    const float4 v = *reinterpret_cast<const float4*>(
        x + (size_t)b * Cq * HWq + (size_t)ch * HWq + pos);
    *reinterpret_cast<float4*>(
        out + (size_t)b * 4 * HWq + (size_t)(1 + j) * HWq + pos) = v;
}

extern "C" void kernel_launch(void* const* d_in, const int* in_sizes, int n_in,
                              void* d_out, int out_size) {
    const float* x     = (const float*)d_in[0];
    const float* Wg    = (const float*)d_in[1];
    const float* bg    = (const float*)d_in[2];
    const float* Wt    = (const float*)d_in[3];
    const float* bt    = (const float*)d_in[4];
    const float* Wp    = (const float*)d_in[5];
    const float* bp    = (const float*)d_in[6];
    const float* Wf    = (const float*)d_in[7];
    const float* bf    = (const float*)d_in[8];
    const float* Wz    = (const float*)d_in[9];
    const float* bz    = (const float*)d_in[10];
    const float* gamma = (const float*)d_in[11];
    const float* beta  = (const float*)d_in[12];
    const float* W3    = (const float*)d_in[13];
    float* out = (float*)d_out;

    k1_fused<<<Bq * 32, 128>>>(x, W3, out);
    k2a_reduce<<<Bq, 256>>>();
    k2b_pipeline<<<1, 256>>>(Wg, bg, Wt, bt, Wp, bp, Wf, bf, Wz, bz, gamma, beta);
    k3_gather<<<Bq * 3 * 16, 256>>>(x, out);
}

// round 2
// speedup vs baseline: 1.9366x; 1.9366x over previous
#include <cuda_runtime.h>
#include <math.h>

#define Bq     16
#define Cq     256
#define HWq    16384
#define INTERq 128
#define K1_CHUNKS 64           // spatial chunks per batch sample
#define K1_THREADS 128         // chunk = 128 thr * 2 floats = 256 floats

// scratch
__device__ float g_scratch[Bq * K1_CHUNKS * Cq];  // per-block channel partials [b][blk][c] (1 MB)
__device__ float g_p [Bq * Cq];                   // pooled means
__device__ float g_wy[Bq * Cq];                   // pre-BN activations
__device__ int   g_idx[Bq * 3];                   // top-3 channels per sample

__device__ __forceinline__ float gelu_exact(float v) {
    return 0.5f * v * (1.0f + erff(v * 0.70710678118654752f));
}

__device__ __forceinline__ float warp_sum(float s) {
    s += __shfl_down_sync(0xffffffffu, s, 16);
    s += __shfl_down_sync(0xffffffffu, s, 8);
    s += __shfl_down_sync(0xffffffffu, s, 4);
    s += __shfl_down_sync(0xffffffffu, s, 2);
    s += __shfl_down_sync(0xffffffffu, s, 1);
    return s;
}

// ---------------------------------------------------------------------------
// K1: single streaming pass over x (256 MB).
//   grid = B*64 blocks x 128 threads; thread owns 2 pixels (float2).
//   Per channel: FMA into per-pixel W3-dot (for GELU out ch0) + warp-reduced
//   channel partial. Depth-4 explicit prefetch keeps >=4 LDGs in flight.
// ---------------------------------------------------------------------------
__global__ __launch_bounds__(K1_THREADS) void k1_fused(const float* __restrict__ x,
                                                       const float* __restrict__ W3,
                                                       float* __restrict__ out) {
    __shared__ float sw3[Cq];
    __shared__ float sps[Cq * 4];

    const int b    = blockIdx.x >> 6;
    const int blk  = blockIdx.x & 63;
    const int t    = threadIdx.x;
    const int lane = t & 31;
    const int warp = t >> 5;

    for (int i = t; i < Cq; i += K1_THREADS) sw3[i] = W3[i];
    __syncthreads();

    const float* xb = x + (size_t)b * Cq * HWq + (size_t)blk * 256 + (size_t)t * 2;

#define LD2(c) (*reinterpret_cast<const float2*>(xb + (size_t)(c) * HWq))

    float2 acc = make_float2(0.f, 0.f);
    float2 v0 = LD2(0), v1 = LD2(1), v2 = LD2(2), v3 = LD2(3);

    for (int c = 0; c < Cq; c += 4) {
        float2 n0, n1, n2, n3;
        if (c + 4 < Cq) { n0 = LD2(c + 4); n1 = LD2(c + 5); n2 = LD2(c + 6); n3 = LD2(c + 7); }
        else            { n0 = n1 = n2 = n3 = make_float2(0.f, 0.f); }

#define PROC(V, CC)                                                      \
        {                                                                \
            const float w = sw3[CC];                                     \
            acc.x = fmaf((V).x, w, acc.x);                               \
            acc.y = fmaf((V).y, w, acc.y);                               \
            float s = (V).x + (V).y;                                     \
            s = warp_sum(s);                                             \
            if (lane == 0) sps[(CC) * 4 + warp] = s;                     \
        }
        PROC(v0, c + 0); PROC(v1, c + 1); PROC(v2, c + 2); PROC(v3, c + 3);
#undef PROC
        v0 = n0; v1 = n1; v2 = n2; v3 = n3;
    }
#undef LD2
    __syncthreads();

    for (int c = t; c < Cq; c += K1_THREADS)
        g_scratch[((size_t)(b * K1_CHUNKS + blk)) * Cq + c] =
            (sps[c * 4 + 0] + sps[c * 4 + 1]) + (sps[c * 4 + 2] + sps[c * 4 + 3]);

    float2 o;
    o.x = gelu_exact(acc.x);
    o.y = gelu_exact(acc.y);
    *reinterpret_cast<float2*>(out + (size_t)b * 4 * HWq + (size_t)blk * 256 + (size_t)t * 2) = o;
}

// ---------------------------------------------------------------------------
// K2: one block per batch sample (16 blocks x 256 threads).
//   Reduce 64 partials -> p (coalesced), then warp-per-column coalesced dots:
//   g/theta/phi projections, f = relu([th,ph].Wf + bf), wy = f*(g.Wz) + bz.
// ---------------------------------------------------------------------------
__device__ __forceinline__ void proj_cols(const float* __restrict__ W,
                                          const float* __restrict__ bias,
                                          const float* sp, float* dst,
                                          int warp, int lane) {
    // warp handles columns [warp*16, warp*16+16); dot over 256 with coalesced loads
    #pragma unroll 2
    for (int i = 0; i < 16; ++i) {
        const int col = warp * 16 + i;
        float a = 0.f;
        #pragma unroll
        for (int k = 0; k < 8; ++k) {
            const int idx = k * 32 + lane;
            a = fmaf(__ldg(W + col * Cq + idx), sp[idx], a);
        }
        a = warp_sum(a);
        if (lane == 0) dst[col] = a + bias[col];
    }
}

__global__ __launch_bounds__(256) void k2_perbatch(
    const float* __restrict__ Wg, const float* __restrict__ bg,
    const float* __restrict__ Wt, const float* __restrict__ bt,
    const float* __restrict__ Wp, const float* __restrict__ bp,
    const float* __restrict__ Wf, const float* __restrict__ bf,
    const float* __restrict__ Wz, const float* __restrict__ bz)
{
    __shared__ float sp[Cq];
    __shared__ float s_g[INTERq], s_th[INTERq], s_ph[INTERq];
    __shared__ float sf_sh;

    const int b    = blockIdx.x;
    const int t    = threadIdx.x;
    const int lane = t & 31;
    const int warp = t >> 5;

    // pooled mean: thread t = channel t; 64 coalesced partial loads
    {
        const float* sc = g_scratch + (size_t)b * K1_CHUNKS * Cq;
        float s = 0.f;
        #pragma unroll
        for (int k = 0; k < K1_CHUNKS; ++k) s += sc[k * Cq + t];
        const float p = s * (1.0f / (float)HWq);
        sp[t] = p;
        g_p[b * Cq + t] = p;
    }
    __syncthreads();

    proj_cols(Wg, bg, sp, s_g,  warp, lane);
    proj_cols(Wt, bt, sp, s_th, warp, lane);
    proj_cols(Wp, bp, sp, s_ph, warp, lane);
    __syncthreads();

    // f = relu([theta, phi] . Wf + bf)
    if (warp == 0) {
        float a = 0.f;
        #pragma unroll
        for (int k = 0; k < 8; ++k) {
            const int i = k * 32 + lane;
            const float v = (i < INTERq) ? s_th[i] : s_ph[i - INTERq];
            a = fmaf(v, __ldg(Wf + i), a);
        }
        a = warp_sum(a);
        if (lane == 0) sf_sh = fmaxf(a + bf[0], 0.f);
    }
    __syncthreads();
    const float f = sf_sh;

    // wy[col] = f * (g . Wz[col]) + bz[col]; warp handles 32 of 256 cols
    #pragma unroll 2
    for (int i = 0; i < 32; ++i) {
        const int col = warp * 32 + i;
        float a = 0.f;
        #pragma unroll
        for (int k = 0; k < 4; ++k) {
            const int idx = k * 32 + lane;
            a = fmaf(__ldg(Wz + col * INTERq + idx), s_g[idx], a);
        }
        a = warp_sum(a);
        if (lane == 0) g_wy[b * Cq + col] = fmaf(f, a, bz[col]);
    }
}

// ---------------------------------------------------------------------------
// K3: single block, 512 threads. BatchNorm over batch + residual, then
//     warp-per-sample top-3 via shuffle-argmax (ties -> lowest index).
// ---------------------------------------------------------------------------
__global__ __launch_bounds__(512) void k3_bn_topk(const float* __restrict__ gamma,
                                                  const float* __restrict__ beta) {
    __shared__ float sz[Bq * Cq];
    const int t = threadIdx.x;

    if (t < Cq) {
        const int c = t;
        float vals[Bq];
        #pragma unroll
        for (int b = 0; b < Bq; ++b) vals[b] = g_wy[b * Cq + c];
        float m = 0.f;
        #pragma unroll
        for (int b = 0; b < Bq; ++b) m += vals[b];
        m *= (1.0f / (float)Bq);
        float var = 0.f;
        #pragma unroll
        for (int b = 0; b < Bq; ++b) { const float d = vals[b] - m; var = fmaf(d, d, var); }
        var *= (1.0f / (float)Bq);
        const float inv = rsqrtf(var + 1e-5f);
        const float ga = gamma[c], be = beta[c];
        #pragma unroll
        for (int b = 0; b < Bq; ++b)
            sz[b * Cq + c] = fmaf(ga * (vals[b] - m), inv, be) + g_p[b * Cq + c];
    }
    __syncthreads();

    // sigmoid monotone -> top-k on z == top-k on scores
    const int warp = t >> 5;   // 16 warps = 16 samples
    const int lane = t & 31;
    {
        float v[8];
        const int base = warp * Cq;
        #pragma unroll
        for (int k = 0; k < 8; ++k) v[k] = sz[base + k * 32 + lane];

        for (int j = 0; j < 3; ++j) {
            float bv = -INFINITY;
            int   bi = 0x7fffffff;
            #pragma unroll
            for (int k = 0; k < 8; ++k) {
                const int idx = k * 32 + lane;
                if (v[k] > bv) { bv = v[k]; bi = idx; }
            }
            #pragma unroll
            for (int off = 16; off > 0; off >>= 1) {
                const float ov = __shfl_down_sync(0xffffffffu, bv, off);
                const int   oi = __shfl_down_sync(0xffffffffu, bi, off);
                if (ov > bv || (ov == bv && oi < bi)) { bv = ov; bi = oi; }
            }
            bi = __shfl_sync(0xffffffffu, bi, 0);
            if (lane == 0) g_idx[warp * 3 + j] = bi;
            const int kk = bi >> 5;
            if ((bi & 31) == lane) {
                #pragma unroll
                for (int k = 0; k < 8; ++k) if (k == kk) v[k] = -INFINITY;
            }
        }
    }
}

// ---------------------------------------------------------------------------
// K4: gather top-3 channels into output channels 1..3.
// ---------------------------------------------------------------------------
__global__ __launch_bounds__(256) void k4_gather(const float* __restrict__ x,
                                                 float* __restrict__ out) {
    const int q    = blockIdx.x >> 4;   // b*3 + j
    const int part = blockIdx.x & 15;
    const int b = q / 3, j = q % 3;
    const int ch = g_idx[b * 3 + j];
    const size_t pos = (size_t)part * 1024 + (size_t)threadIdx.x * 4;
    const float4 v = *reinterpret_cast<const float4*>(
        x + (size_t)b * Cq * HWq + (size_t)ch * HWq + pos);
    *reinterpret_cast<float4*>(
        out + (size_t)b * 4 * HWq + (size_t)(1 + j) * HWq + pos) = v;
}

extern "C" void kernel_launch(void* const* d_in, const int* in_sizes, int n_in,
                              void* d_out, int out_size) {
    const float* x     = (const float*)d_in[0];
    const float* Wg    = (const float*)d_in[1];
    const float* bg    = (const float*)d_in[2];
    const float* Wt    = (const float*)d_in[3];
    const float* bt    = (const float*)d_in[4];
    const float* Wp    = (const float*)d_in[5];
    const float* bp    = (const float*)d_in[6];
    const float* Wf    = (const float*)d_in[7];
    const float* bf    = (const float*)d_in[8];
    const float* Wz    = (const float*)d_in[9];
    const float* bz    = (const float*)d_in[10];
    const float* gamma = (const float*)d_in[11];
    const float* beta  = (const float*)d_in[12];
    const float* W3    = (const float*)d_in[13];
    float* out = (float*)d_out;

    k1_fused<<<Bq * K1_CHUNKS, K1_THREADS>>>(x, W3, out);
    k2_perbatch<<<Bq, 256>>>(Wg, bg, Wt, bt, Wp, bp, Wf, bf, Wz, bz);
    k3_bn_topk<<<1, 512>>>(gamma, beta);
    k4_gather<<<Bq * 3 * 16, 256>>>(x, out);
}

// round 4
// speedup vs baseline: 2.0957x; 1.0822x over previous
#include <cuda_runtime.h>
#include <math.h>

#define Bq     16
#define Cq     256
#define HWq    16384
#define INTERq 128
#define CHUNKS 128               // pixel chunks per sample (128 px each)

// scratch (no atomics anywhere)
__device__ float g_csum[Bq * CHUNKS * Cq];  // [b][chunk][c] partial channel sums (2 MB)
__device__ float g_p   [Bq * Cq];           // pooled means
__device__ float g_wy  [Bq * Cq];           // pre-BN activations
__device__ int   g_idx [Bq * 3];            // top-3 channels per sample

__device__ __forceinline__ float gelu_exact(float v) {
    return 0.5f * v * (1.0f + erff(v * 0.70710678118654752f));
}

__device__ __forceinline__ float warp_sum(float s) {
    s += __shfl_down_sync(0xffffffffu, s, 16);
    s += __shfl_down_sync(0xffffffffu, s, 8);
    s += __shfl_down_sync(0xffffffffu, s, 4);
    s += __shfl_down_sync(0xffffffffu, s, 2);
    s += __shfl_down_sync(0xffffffffu, s, 1);
    return s;
}

// ---------------------------------------------------------------------------
// K1: single streaming pass over x. Block = (b, 128-pixel chunk); 256 threads
//     = 32 channel-groups (cw) x 8 pixel-slots (pw). Thread loads 8 channels
//     x 4 float4; channel sums AND pixel dots accumulate in REGISTERS.
//     Epilogue: two small conflict-free shared reductions; writes out ch0
//     (GELU) and per-chunk channel partials. Zero shuffles in hot loop.
// ---------------------------------------------------------------------------
__global__ __launch_bounds__(256) void k1_stream(const float* __restrict__ x,
                                                 const float* __restrict__ W3,
                                                 float* __restrict__ out) {
    __shared__ float sw[Cq];
    __shared__ float scs[Cq][8];        // [channel][pw]   : 8 KB
    __shared__ float sdot[4][32][32];   // [seg][cw][pix%32]: 16 KB

    const int b     = blockIdx.x >> 7;
    const int chunk = blockIdx.x & 127;
    const int t  = threadIdx.x;
    const int cw = t >> 3;              // 0..31 channel group
    const int pw = t & 7;               // 0..7 pixel slot

    for (int i = t; i < Cq; i += 256) sw[i] = W3[i];
    __syncthreads();

    const float* xb = x + ((size_t)b * Cq + (size_t)cw * 8) * HWq
                        + (size_t)chunk * 128 + (size_t)pw * 4;

    float4 dot[4];
    #pragma unroll
    for (int s = 0; s < 4; ++s) dot[s] = make_float4(0.f, 0.f, 0.f, 0.f);
    float cs[8];
    #pragma unroll
    for (int j = 0; j < 8; ++j) cs[j] = 0.f;

    #pragma unroll
    for (int j = 0; j < 8; ++j) {
        const float w = sw[cw * 8 + j];
        const float* xc = xb + (size_t)j * HWq;
        #pragma unroll
        for (int s = 0; s < 4; ++s) {
            const float4 v = *reinterpret_cast<const float4*>(xc + s * 32);
            dot[s].x = fmaf(v.x, w, dot[s].x);
            dot[s].y = fmaf(v.y, w, dot[s].y);
            dot[s].z = fmaf(v.z, w, dot[s].z);
            dot[s].w = fmaf(v.w, w, dot[s].w);
            cs[j] += (v.x + v.y) + (v.z + v.w);
        }
    }

    #pragma unroll
    for (int j = 0; j < 8; ++j) scs[cw * 8 + j][pw] = cs[j];
    #pragma unroll
    for (int s = 0; s < 4; ++s)
        *reinterpret_cast<float4*>(&sdot[s][cw][pw * 4]) = dot[s];
    __syncthreads();

    // channel-sum finalize: thread t = channel t; 8 adds; coalesced store
    {
        float s = 0.f;
        #pragma unroll
        for (int k = 0; k < 8; ++k) s += scs[t][k];
        g_csum[((size_t)b * CHUNKS + chunk) * Cq + t] = s;
    }

    // dot finalize: threads 0..127 = local pixel; sum 32 cw partials; GELU
    if (t < 128) {
        const int s = t >> 5, q = t & 31;
        float d = 0.f;
        #pragma unroll
        for (int k = 0; k < 32; ++k) d += sdot[s][k][q];
        out[(size_t)b * 4 * HWq + (size_t)chunk * 128 + t] = gelu_exact(d);
    }
}

// ---------------------------------------------------------------------------
// K2: one block per batch sample (16 blocks x 256 threads).
//   Reduce 128 chunk partials -> p, then coalesced warp dots:
//   g/theta/phi projections, f = relu([th,ph].Wf + bf), wy = f*(g.Wz) + bz.
// ---------------------------------------------------------------------------
__device__ __forceinline__ void proj_cols(const float* __restrict__ W,
                                          const float* __restrict__ bias,
                                          const float* sp, float* dst,
                                          int warp, int lane) {
    #pragma unroll 2
    for (int i = 0; i < 16; ++i) {
        const int col = warp * 16 + i;
        float a = 0.f;
        #pragma unroll
        for (int k = 0; k < 8; ++k) {
            const int idx = k * 32 + lane;
            a = fmaf(__ldg(W + col * Cq + idx), sp[idx], a);
        }
        a = warp_sum(a);
        if (lane == 0) dst[col] = a + bias[col];
    }
}

__global__ __launch_bounds__(256) void k2_perbatch(
    const float* __restrict__ Wg, const float* __restrict__ bg,
    const float* __restrict__ Wt, const float* __restrict__ bt,
    const float* __restrict__ Wp, const float* __restrict__ bp,
    const float* __restrict__ Wf, const float* __restrict__ bf,
    const float* __restrict__ Wz, const float* __restrict__ bz)
{
    __shared__ float sp[Cq];
    __shared__ float s_g[INTERq], s_th[INTERq], s_ph[INTERq];
    __shared__ float sf_sh;

    const int b    = blockIdx.x;
    const int t    = threadIdx.x;
    const int lane = t & 31;
    const int warp = t >> 5;

    {
        const float* cs = g_csum + (size_t)b * CHUNKS * Cq + t;
        float s = 0.f;
        #pragma unroll 8
        for (int k = 0; k < CHUNKS; ++k) s += cs[(size_t)k * Cq];
        const float p = s * (1.0f / (float)HWq);
        sp[t] = p;
        g_p[b * Cq + t] = p;
    }
    __syncthreads();

    proj_cols(Wg, bg, sp, s_g,  warp, lane);
    proj_cols(Wt, bt, sp, s_th, warp, lane);
    proj_cols(Wp, bp, sp, s_ph, warp, lane);
    __syncthreads();

    if (warp == 0) {
        float a = 0.f;
        #pragma unroll
        for (int k = 0; k < 8; ++k) {
            const int i = k * 32 + lane;
            const float v = (i < INTERq) ? s_th[i] : s_ph[i - INTERq];
            a = fmaf(v, __ldg(Wf + i), a);
        }
        a = warp_sum(a);
        if (lane == 0) sf_sh = fmaxf(a + bf[0], 0.f);
    }
    __syncthreads();
    const float f = sf_sh;

    #pragma unroll 2
    for (int i = 0; i < 32; ++i) {
        const int col = warp * 32 + i;
        float a = 0.f;
        #pragma unroll
        for (int k = 0; k < 4; ++k) {
            const int idx = k * 32 + lane;
            a = fmaf(__ldg(Wz + col * INTERq + idx), s_g[idx], a);
        }
        a = warp_sum(a);
        if (lane == 0) g_wy[b * Cq + col] = fmaf(f, a, bz[col]);
    }
}

// ---------------------------------------------------------------------------
// K3: single block, 512 threads. BN over batch + residual, warp-per-sample
//     top-3 via shuffle-argmax (ties -> lowest index, matches lax.top_k).
// ---------------------------------------------------------------------------
__global__ __launch_bounds__(512) void k3_bn_topk(const float* __restrict__ gamma,
                                                  const float* __restrict__ beta) {
    __shared__ float sz[Bq * Cq];
    const int t = threadIdx.x;

    if (t < Cq) {
        const int c = t;
        float vals[Bq];
        #pragma unroll
        for (int b = 0; b < Bq; ++b) vals[b] = g_wy[b * Cq + c];
        float m = 0.f;
        #pragma unroll
        for (int b = 0; b < Bq; ++b) m += vals[b];
        m *= (1.0f / (float)Bq);
        float var = 0.f;
        #pragma unroll
        for (int b = 0; b < Bq; ++b) { const float d = vals[b] - m; var = fmaf(d, d, var); }
        var *= (1.0f / (float)Bq);
        const float inv = rsqrtf(var + 1e-5f);
        const float ga = gamma[c], be = beta[c];
        #pragma unroll
        for (int b = 0; b < Bq; ++b)
            sz[b * Cq + c] = fmaf(ga * (vals[b] - m), inv, be) + g_p[b * Cq + c];
    }
    __syncthreads();

    const int warp = t >> 5;   // 16 warps = 16 samples
    const int lane = t & 31;
    {
        float v[8];
        const int base = warp * Cq;
        #pragma unroll
        for (int k = 0; k < 8; ++k) v[k] = sz[base + k * 32 + lane];

        for (int j = 0; j < 3; ++j) {
            float bv = -INFINITY;
            int   bi = 0x7fffffff;
            #pragma unroll
            for (int k = 0; k < 8; ++k) {
                const int idx = k * 32 + lane;
                if (v[k] > bv) { bv = v[k]; bi = idx; }
            }
            #pragma unroll
            for (int off = 16; off > 0; off >>= 1) {
                const float ov = __shfl_down_sync(0xffffffffu, bv, off);
                const int   oi = __shfl_down_sync(0xffffffffu, bi, off);
                if (ov > bv || (ov == bv && oi < bi)) { bv = ov; bi = oi; }
            }
            bi = __shfl_sync(0xffffffffu, bi, 0);
            if (lane == 0) g_idx[warp * 3 + j] = bi;
            const int kk = bi >> 5;
            if ((bi & 31) == lane) {
                #pragma unroll
                for (int k = 0; k < 8; ++k) if (k == kk) v[k] = -INFINITY;
            }
        }
    }
}

// ---------------------------------------------------------------------------
// K4: gather top-3 channels into output channels 1..3.
// ---------------------------------------------------------------------------
__global__ __launch_bounds__(256) void k4_gather(const float* __restrict__ x,
                                                 float* __restrict__ out) {
    const int q    = blockIdx.x >> 4;   // b*3 + j
    const int part = blockIdx.x & 15;
    const int b = q / 3, j = q % 3;
    const int ch = g_idx[b * 3 + j];
    const size_t pos = (size_t)part * 1024 + (size_t)threadIdx.x * 4;
    const float4 v = *reinterpret_cast<const float4*>(
        x + ((size_t)b * Cq + ch) * HWq + pos);
    *reinterpret_cast<float4*>(
        out + ((size_t)b * 4 + 1 + j) * HWq + pos) = v;
}

extern "C" void kernel_launch(void* const* d_in, const int* in_sizes, int n_in,
                              void* d_out, int out_size) {
    const float* x     = (const float*)d_in[0];
    const float* Wg    = (const float*)d_in[1];
    const float* bg    = (const float*)d_in[2];
    const float* Wt    = (const float*)d_in[3];
    const float* bt    = (const float*)d_in[4];
    const float* Wp    = (const float*)d_in[5];
    const float* bp    = (const float*)d_in[6];
    const float* Wf    = (const float*)d_in[7];
    const float* bf    = (const float*)d_in[8];
    const float* Wz    = (const float*)d_in[9];
    const float* bz    = (const float*)d_in[10];
    const float* gamma = (const float*)d_in[11];
    const float* beta  = (const float*)d_in[12];
    const float* W3    = (const float*)d_in[13];
    float* out = (float*)d_out;

    k1_stream<<<Bq * CHUNKS, 256>>>(x, W3, out);
    k2_perbatch<<<Bq, 256>>>(Wg, bg, Wt, bt, Wp, bp, Wf, bf, Wz, bz);
    k3_bn_topk<<<1, 512>>>(gamma, beta);
    k4_gather<<<Bq * 3 * 16, 256>>>(x, out);
}